// round 15
// baseline (speedup 1.0000x reference)
#include <cuda_runtime.h>

#define HH    56
#define WW    56
#define CIN   64
#define COUT  64
#define TILE  8
#define NB    16
#define QSPLIT 4                       // ci quarters (2 chunks per CTA)
#define PIX   (NB * COUT * HH * WW)    // floats per partial = 12,845,056

// partial[q][n][co][h][w], NEGATIVE sums; 51.4 MB static scratch
__device__ float g_partial[QSPLIT * PIX];

// CTA: one (n, ci-quarter), one 8x8 tile, ALL 64 output channels.
// 128 threads: py = tid&7, cg = tid>>3 -> 4 channels each.
// FFMA-imm formulation (rt_SMSP=1, 2x port throughput of FADD):
//   smem holds x2 = 2*x (exact)
//   d   = fmaf(w, -2.0f, x2)          -> FFMA-imm, = 2(x-w), single rounding
//   acc = fmaf(fabsf(d), -0.5f, acc)  -> FFMA-imm, = acc - |x-w| bit-exact
__global__ void __launch_bounds__(128, 8)
adder2d_partial_kernel(const float* __restrict__ x,
                       const float* __restrict__ w)
{
    __shared__ __align__(16) float sx2[8][10][12];  // 2*x, 8ci x 10 x 12, 3.84 KB
    __shared__ __align__(16) float swn[8][9][64];   // plain weights, 18.4 KB

    const int tid  = threadIdx.x;
    const int py   = tid & 7;
    const int co4  = (tid >> 3) * 4;

    const int tx0 = blockIdx.x * TILE;
    const int ty0 = blockIdx.y * TILE;
    const int n   = blockIdx.z >> 2;
    const int q   = blockIdx.z & 3;      // ci quarter: chunks 2q, 2q+1

    const float* xn = x + (size_t)n * CIN * HH * WW;

    float acc[4][8];
    #pragma unroll
    for (int c = 0; c < 4; ++c)
        #pragma unroll
        for (int p = 0; p < 8; ++p) acc[c][p] = 0.0f;

    for (int cc = 0; cc < 2; ++cc) {
        const int c8 = q * 2 + cc;
        __syncthreads();   // previous chunk's readers done

        // ---- stage x chunk (pre-scaled by 2): 8 ci x 10 rows x 12 cols ----
        #pragma unroll
        for (int it = 0; it < 8; ++it) {              // 960 / 128 = 7.5
            int idx = it * 128 + tid;
            if (idx < 960) {
                int ci_l = idx / 120;
                int r    = idx - ci_l * 120;
                int row  = r / 12;
                int col  = r - row * 12;
                int gy   = ty0 + row - 1;
                int gx   = tx0 + col - 1;
                float v  = 0.0f;
                if (col < 10 && (unsigned)gy < (unsigned)HH && (unsigned)gx < (unsigned)WW)
                    v = xn[((c8 * 8 + ci_l) * HH + gy) * WW + gx];
                sx2[ci_l][row][col] = 2.0f * v;       // exact scaling
            }
        }
        // ---- stage weights: 8 ci x 9 k x 64 co, plain copy ----
        #pragma unroll
        for (int it = 0; it < 36; ++it) {             // 4608 / 128
            int idx  = it * 128 + tid;
            int co   = idx & 63;
            int rest = idx >> 6;                      // 0..71
            int k    = rest % 9;
            int ci_l = rest / 9;
            swn[ci_l][k][co] = w[(co * CIN + c8 * 8 + ci_l) * 9 + k];
        }
        __syncthreads();

        // ---- compute: per (ci,kh): 3 x-LDS.128 + 3 x (1 w-LDS.128 + 64 FFMA-imm) ----
        for (int ci_l = 0; ci_l < 8; ++ci_l) {
            #pragma unroll
            for (int kh = 0; kh < 3; ++kh) {
                const float4* rp = (const float4*)&sx2[ci_l][py + kh][0];
                float4 a = rp[0], b = rp[1], e = rp[2];
                float xr[12] = {a.x, a.y, a.z, a.w, b.x, b.y, b.z, b.w,
                                e.x, e.y, e.z, e.w};

                #pragma unroll
                for (int kw = 0; kw < 3; ++kw) {
                    float4 w4 = *(const float4*)&swn[ci_l][kh * 3 + kw][co4];
                    #pragma unroll
                    for (int px = 0; px < 8; ++px) {
                        float xv2 = xr[px + kw];                 // 2*x
                        float d0 = fmaf(w4.x, -2.0f, xv2);       // FFMA-imm: 2(x-w)
                        float d1 = fmaf(w4.y, -2.0f, xv2);
                        float d2 = fmaf(w4.z, -2.0f, xv2);
                        float d3 = fmaf(w4.w, -2.0f, xv2);
                        acc[0][px] = fmaf(fabsf(d0), -0.5f, acc[0][px]); // FFMA-imm
                        acc[1][px] = fmaf(fabsf(d1), -0.5f, acc[1][px]);
                        acc[2][px] = fmaf(fabsf(d2), -0.5f, acc[2][px]);
                        acc[3][px] = fmaf(fabsf(d3), -0.5f, acc[3][px]);
                    }
                }
            }
        }
    }

    // ---- epilogue: negative partial sums -> scratch[q] ----
    #pragma unroll
    for (int c = 0; c < 4; ++c) {
        float* o = g_partial + (size_t)q * PIX
                 + (((size_t)n * COUT + co4 + c) * HH + (ty0 + py)) * WW + tx0;
        ((float4*)o)[0] = make_float4(acc[c][0], acc[c][1], acc[c][2], acc[c][3]);
        ((float4*)o)[1] = make_float4(acc[c][4], acc[c][5], acc[c][6], acc[c][7]);
    }
}

// out = p0 + p1 + p2 + p3 (partials already negative), float4-vectorized
__global__ void __launch_bounds__(256)
adder2d_reduce_kernel(float* __restrict__ out)
{
    const size_t i = (size_t)blockIdx.x * 256 + threadIdx.x;   // float4 index
    const float4* p = (const float4*)g_partial;
    const size_t Q = PIX / 4;                                   // 3,211,264

    float4 a = p[i], b = p[i + Q], c = p[i + 2 * Q], d = p[i + 3 * Q];
    float4 r;
    r.x = (a.x + b.x) + (c.x + d.x);
    r.y = (a.y + b.y) + (c.y + d.y);
    r.z = (a.z + b.z) + (c.z + d.z);
    r.w = (a.w + b.w) + (c.w + d.w);
    ((float4*)out)[i] = r;
}

extern "C" void kernel_launch(void* const* d_in, const int* in_sizes, int n_in,
                              void* d_out, int out_size)
{
    const float* x = (const float*)d_in[0];
    const float* w = (const float*)d_in[1];
    float* out     = (float*)d_out;

    dim3 grid(WW / TILE, HH / TILE, NB * QSPLIT);   // 7 x 7 x 64 = 3136 CTAs
    adder2d_partial_kernel<<<grid, 128>>>(x, w);

    adder2d_reduce_kernel<<<PIX / 4 / 256, 256>>>(out);   // 12544 blocks
}

// round 16
// speedup vs baseline: 1.5997x; 1.5997x over previous
#include <cuda_runtime.h>

#define HH    56
#define WW    56
#define CIN   64
#define COUT  64
#define TILE  8
#define NB    16
#define QSPLIT 2                       // ci halves (4 chunks per CTA)
#define PIX   (NB * COUT * HH * WW)    // floats per partial = 12,845,056

// partial[q][n][co][h][w], NEGATIVE sums; 2 x 12.85M floats = 25.7 MB scratch
__device__ float g_partial[QSPLIT * PIX];

// CTA: one (n, ci-half), one 8x8 tile, ALL 64 output channels.
// 128 threads: py = tid&7 (tile row), cg = tid>>3 -> 4 channels each.
// Scalar FADD formulation: acc -= fabsf(x - w) -> 2 FADD/term (fma port, rt2).
// This sits exactly on the fma-port floor (~193us kernel-1); QSPLIT=2 minimizes
// the partial-sum traffic + reduce cost around it.
__global__ void __launch_bounds__(128, 8)
adder2d_partial_kernel(const float* __restrict__ x,
                       const float* __restrict__ w)
{
    __shared__ __align__(16) float sx[8][10][12];   // 8 ci x 10 rows x 12 cols, 3.84 KB
    __shared__ __align__(16) float swn[8][9][64];   // weights [ci][k][co], 18.4 KB

    const int tid  = threadIdx.x;
    const int py   = tid & 7;
    const int co4  = (tid >> 3) * 4;

    const int tx0 = blockIdx.x * TILE;
    const int ty0 = blockIdx.y * TILE;
    const int n   = blockIdx.z >> 1;
    const int q   = blockIdx.z & 1;      // ci half: chunks 4q .. 4q+3

    const float* xn = x + (size_t)n * CIN * HH * WW;

    float acc[4][8];
    #pragma unroll
    for (int c = 0; c < 4; ++c)
        #pragma unroll
        for (int p = 0; p < 8; ++p) acc[c][p] = 0.0f;

    for (int cc = 0; cc < 4; ++cc) {
        const int c8 = q * 4 + cc;
        __syncthreads();   // previous chunk's readers done

        // ---- stage x chunk: 8 ci x 10 rows x 12 cols (cols 10,11 + halo zero) ----
        #pragma unroll
        for (int it = 0; it < 8; ++it) {              // 960 / 128 = 7.5
            int idx = it * 128 + tid;
            if (idx < 960) {
                int ci_l = idx / 120;
                int r    = idx - ci_l * 120;
                int row  = r / 12;
                int col  = r - row * 12;
                int gy   = ty0 + row - 1;
                int gx   = tx0 + col - 1;
                float v  = 0.0f;
                if (col < 10 && (unsigned)gy < (unsigned)HH && (unsigned)gx < (unsigned)WW)
                    v = xn[((c8 * 8 + ci_l) * HH + gy) * WW + gx];
                sx[ci_l][row][col] = v;
            }
        }
        // ---- stage weights: 8 ci x 9 k x 64 co, plain copy ----
        #pragma unroll
        for (int it = 0; it < 36; ++it) {             // 4608 / 128
            int idx  = it * 128 + tid;
            int co   = idx & 63;
            int rest = idx >> 6;                      // 0..71
            int k    = rest % 9;
            int ci_l = rest / 9;
            swn[ci_l][k][co] = w[(co * CIN + c8 * 8 + ci_l) * 9 + k];
        }
        __syncthreads();

        // ---- compute: per (ci,kh): 3 x-LDS.128 + 3 x (1 w-LDS.128 + 64 FADD) ----
        for (int ci_l = 0; ci_l < 8; ++ci_l) {
            #pragma unroll
            for (int kh = 0; kh < 3; ++kh) {
                const float4* rp = (const float4*)&sx[ci_l][py + kh][0];
                float4 a = rp[0], b = rp[1], e = rp[2];
                float xr[12] = {a.x, a.y, a.z, a.w, b.x, b.y, b.z, b.w,
                                e.x, e.y, e.z, e.w};

                #pragma unroll
                for (int kw = 0; kw < 3; ++kw) {
                    float4 w4 = *(const float4*)&swn[ci_l][kh * 3 + kw][co4];
                    #pragma unroll
                    for (int px = 0; px < 8; ++px) {
                        float xv = xr[px + kw];
                        acc[0][px] -= fabsf(xv - w4.x);   // FADD + FADD(-|.|)
                        acc[1][px] -= fabsf(xv - w4.y);
                        acc[2][px] -= fabsf(xv - w4.z);
                        acc[3][px] -= fabsf(xv - w4.w);
                    }
                }
            }
        }
    }

    // ---- epilogue: negative partial sums -> scratch[q] ----
    #pragma unroll
    for (int c = 0; c < 4; ++c) {
        float* o = g_partial + (size_t)q * PIX
                 + (((size_t)n * COUT + co4 + c) * HH + (ty0 + py)) * WW + tx0;
        ((float4*)o)[0] = make_float4(acc[c][0], acc[c][1], acc[c][2], acc[c][3]);
        ((float4*)o)[1] = make_float4(acc[c][4], acc[c][5], acc[c][6], acc[c][7]);
    }
}

// out = p0 + p1 (partials already negative), float4-vectorized
__global__ void __launch_bounds__(256)
adder2d_reduce_kernel(float* __restrict__ out)
{
    const size_t i = (size_t)blockIdx.x * 256 + threadIdx.x;   // float4 index
    const float4* p = (const float4*)g_partial;
    const size_t Q = PIX / 4;                                   // 3,211,264

    float4 a = p[i], b = p[i + Q];
    float4 r;
    r.x = a.x + b.x;
    r.y = a.y + b.y;
    r.z = a.z + b.z;
    r.w = a.w + b.w;
    ((float4*)out)[i] = r;
}

extern "C" void kernel_launch(void* const* d_in, const int* in_sizes, int n_in,
                              void* d_out, int out_size)
{
    const float* x = (const float*)d_in[0];
    const float* w = (const float*)d_in[1];
    float* out     = (float*)d_out;

    dim3 grid(WW / TILE, HH / TILE, NB * QSPLIT);   // 7 x 7 x 32 = 1568 CTAs
    adder2d_partial_kernel<<<grid, 128>>>(x, w);

    adder2d_reduce_kernel<<<PIX / 4 / 256, 256>>>(out);   // 12544 blocks
}

// round 17
// speedup vs baseline: 1.6828x; 1.0519x over previous
#include <cuda_runtime.h>
#include <cuda_fp16.h>

#define HH    56
#define WW    56
#define CIN   64
#define COUT  64
#define TILE  8
#define NB    16
#define QSPLIT 2                       // ci halves (4 chunks per CTA)
#define PIX   (NB * COUT * HH * WW)    // floats per partial = 12,845,056

// partial[q][n][co][h][w], POSITIVE sums; 25.7 MB static scratch
__device__ float g_partial[QSPLIT * PIX];

// CTA: one (n, ci-half), one 8x8 tile, ALL 64 output channels.
// 128 threads: py = tid&7, cg = tid>>3 -> 4 channels each.
// fp16x2 math: per 2 terms 1 HADD2 diff + HABS2 + 1 HADD2 acc -> 2 fma-cyc/term
// (half the fp32 FADD port cost). fp16 accs dumped to fp32 every 2 ci (18 terms)
// to bound accumulation error (~6e-4 worst-case vs 1e-3 threshold).
__global__ void __launch_bounds__(128, 6)
adder2d_partial_kernel(const float* __restrict__ x,
                       const float* __restrict__ w)
{
    // x pre-paired stride-4 in fp16: sxh[ci][row][t] = half2(x[t], x[t+4]),
    // t=0..5, row padded to 8 half2 (32B) for vector loads.  2.56 KB
    __shared__ __align__(16) __half2 sxh[8][10][8];
    // dup negated weights: swdh[ci][k][co] = half2(-w, -w).  18.4 KB
    __shared__ __align__(16) __half2 swdh[8][9][64];

    const int tid  = threadIdx.x;
    const int py   = tid & 7;
    const int co4  = (tid >> 3) * 4;

    const int tx0 = blockIdx.x * TILE;
    const int ty0 = blockIdx.y * TILE;
    const int n   = blockIdx.z >> 1;
    const int q   = blockIdx.z & 1;      // ci half: chunks 4q .. 4q+3

    const float* xn = x + (size_t)n * CIN * HH * WW;

    const __half2 h2zero = __float2half2_rn(0.0f);

    float   accf[4][8];
    #pragma unroll
    for (int c = 0; c < 4; ++c)
        #pragma unroll
        for (int p = 0; p < 8; ++p) accf[c][p] = 0.0f;

    for (int cc = 0; cc < 4; ++cc) {
        const int c8 = q * 4 + cc;
        __syncthreads();   // previous chunk's readers done

        // ---- stage x chunk: 8 ci x 10 rows x 6 stride-4 half2 pairs ----
        #pragma unroll
        for (int it = 0; it < 4; ++it) {              // 480 / 128
            int idx = it * 128 + tid;
            if (idx < 480) {
                int ci_l = idx / 60;
                int r    = idx - ci_l * 60;
                int row  = r / 6;
                int t    = r - row * 6;
                int gy   = ty0 + row - 1;
                int gx0  = tx0 + t - 1;
                float lo = 0.0f, hi = 0.0f;
                if ((unsigned)gy < (unsigned)HH) {
                    const float* base = &xn[((c8 * 8 + ci_l) * HH + gy) * WW];
                    if ((unsigned)gx0 < (unsigned)WW)       lo = base[gx0];
                    if ((unsigned)(gx0 + 4) < (unsigned)WW) hi = base[gx0 + 4];
                }
                sxh[ci_l][row][t] = __floats2half2_rn(lo, hi);
            }
        }
        // ---- stage weights: negated fp16 duplicated pairs ----
        #pragma unroll
        for (int it = 0; it < 36; ++it) {             // 4608 / 128
            int idx  = it * 128 + tid;
            int co   = idx & 63;
            int rest = idx >> 6;                      // 0..71
            int k    = rest % 9;
            int ci_l = rest / 9;
            float wv = -w[(co * CIN + c8 * 8 + ci_l) * 9 + k];
            swdh[ci_l][k][co] = __float2half2_rn(wv);
        }
        __syncthreads();

        // ---- compute: ci processed in pairs; fp16 accs dumped every 2 ci ----
        for (int ci2 = 0; ci2 < 4; ++ci2) {
            __half2 acch[4][4];
            #pragma unroll
            for (int c = 0; c < 4; ++c)
                #pragma unroll
                for (int j = 0; j < 4; ++j) acch[c][j] = h2zero;

            #pragma unroll
            for (int u = 0; u < 2; ++u) {
                const int ci_l = ci2 * 2 + u;
                #pragma unroll
                for (int kh = 0; kh < 3; ++kh) {
                    union { uint4 v; __half2 h[4]; } xa;
                    union { uint2 v; __half2 h[2]; } xb;
                    xa.v = *(const uint4*)&sxh[ci_l][py + kh][0];   // LDS.128
                    xb.v = *(const uint2*)&sxh[ci_l][py + kh][4];   // LDS.64
                    __half2 P[6] = {xa.h[0], xa.h[1], xa.h[2], xa.h[3],
                                    xb.h[0], xb.h[1]};

                    #pragma unroll
                    for (int kw = 0; kw < 3; ++kw) {
                        union { uint4 v; __half2 h[4]; } wd;    // LDS.128
                        wd.v = *(const uint4*)&swdh[ci_l][kh * 3 + kw][co4];
                        #pragma unroll
                        for (int c = 0; c < 4; ++c) {
                            #pragma unroll
                            for (int j = 0; j < 4; ++j) {
                                __half2 d = __hadd2(P[j + kw], wd.h[c]);
                                acch[c][j] = __hadd2(acch[c][j], __habs2(d));
                            }
                        }
                    }
                }
            }

            // dump 18-term fp16 partials into fp32 accumulators
            #pragma unroll
            for (int c = 0; c < 4; ++c)
                #pragma unroll
                for (int j = 0; j < 4; ++j) {
                    float2 f = __half22float2(acch[c][j]);
                    accf[c][j]     += f.x;
                    accf[c][j + 4] += f.y;
                }
        }
    }

    // ---- epilogue: positive partial sums -> scratch[q] ----
    #pragma unroll
    for (int c = 0; c < 4; ++c) {
        float* o = g_partial + (size_t)q * PIX
                 + (((size_t)n * COUT + co4 + c) * HH + (ty0 + py)) * WW + tx0;
        ((float4*)o)[0] = make_float4(accf[c][0], accf[c][1], accf[c][2], accf[c][3]);
        ((float4*)o)[1] = make_float4(accf[c][4], accf[c][5], accf[c][6], accf[c][7]);
    }
}

// out = -(p0 + p1), float4-vectorized
__global__ void __launch_bounds__(256)
adder2d_reduce_kernel(float* __restrict__ out)
{
    const size_t i = (size_t)blockIdx.x * 256 + threadIdx.x;   // float4 index
    const float4* p = (const float4*)g_partial;
    const size_t Q = PIX / 4;                                   // 3,211,264

    float4 a = p[i], b = p[i + Q];
    float4 r;
    r.x = -(a.x + b.x);
    r.y = -(a.y + b.y);
    r.z = -(a.z + b.z);
    r.w = -(a.w + b.w);
    ((float4*)out)[i] = r;
}

extern "C" void kernel_launch(void* const* d_in, const int* in_sizes, int n_in,
                              void* d_out, int out_size)
{
    const float* x = (const float*)d_in[0];
    const float* w = (const float*)d_in[1];
    float* out     = (float*)d_out;

    dim3 grid(WW / TILE, HH / TILE, NB * QSPLIT);   // 7 x 7 x 32 = 1568 CTAs
    adder2d_partial_kernel<<<grid, 128>>>(x, w);

    adder2d_reduce_kernel<<<PIX / 4 / 256, 256>>>(out);   // 12544 blocks
}